// round 9
// baseline (speedup 1.0000x reference)
#include <cuda_runtime.h>
#include <cuda_bf16.h>
#include <cstdint>

// Fan-model nonlinear mixing via mma.sync bf16 + cp.async.bulk stores:
//   out[b,x] = L + (L^2 - Q)/2,  L = sum_p E[b,p] a[p,x],  Q = sum_p E^2 a^2
// bf16 hi/lo split, K stacked (al*el dropped):
//   L: ah*eh + al*eh + ah*el     Q: sh*fh + sl*fh + sh*fl
// mma.m16n8k16: M=16 px, N=8 bands. CTA = 8 warps x 16 px = 128 px, 28 octets.
// R9: output staged in smem (conflict-free) and written by cp.async.bulk
// S2G (TMA pipe) -> store wavefronts leave L1. B-table in fragment order
// (2x LDS.128 per octet instead of 8x LDS.32).

#define NPIX (512 * 512)
#define NP   12
#define NB   224
#define NOCT (NB / 8)            // 28

// smem layout
#define SM_TBLE 0                // 28*32*16 = 14336
#define SM_TBLF 14336            // 14336
#define SM_BUF  28672            // 2 x 8 x 528B = 8448
#define BUF_PITCH_W 132          // floats per band row (128 + 4 pad)
#define BUF_BYTES   (8 * BUF_PITCH_W * 4)   // 4224 per buffer
#define SM_TOTAL (28672 + 2 * BUF_BYTES)    // 37120

// fragment-order B tables: [mat][octet][lane] = uint4 {b0,b1 / lo0,lo1}
__device__ __align__(16) uint4 g_tbl[2][NOCT][32];

static __device__ __forceinline__ uint32_t pk(float lo, float hi) {
    uint32_t r;   // {lo -> low half, hi -> high half}
    asm("cvt.rn.bf16x2.f32 %0, %1, %2;" : "=r"(r) : "f"(hi), "f"(lo));
    return r;
}

__global__ void prep_kernel(const float* __restrict__ E) {
    int idx = blockIdx.x * blockDim.x + threadIdx.x;   // 28*32 slots
    if (idx >= NOCT * 32) return;
    int o = idx >> 5, t = idx & 31;
    int g = t >> 2, i = t & 3;
    int band = o * 8 + g;

    float eh[16], el[16], fh[16], fl[16];
#pragma unroll
    for (int p = 0; p < 16; p++) {
        float e = (p < NP) ? E[band * NP + p] : 0.0f;
        float f = e * e;
        float ehp = __bfloat162float(__float2bfloat16(e));
        float fhp = __bfloat162float(__float2bfloat16(f));
        eh[p] = e;  el[p] = e - ehp;
        fh[p] = f;  fl[p] = f - fhp;
    }
    uint4 ve, vf;
    ve.x = pk(eh[2 * i], eh[2 * i + 1]);
    ve.y = pk(eh[8 + 2 * i], eh[8 + 2 * i + 1]);
    ve.z = pk(el[2 * i], el[2 * i + 1]);
    ve.w = pk(el[8 + 2 * i], el[8 + 2 * i + 1]);
    vf.x = pk(fh[2 * i], fh[2 * i + 1]);
    vf.y = pk(fh[8 + 2 * i], fh[8 + 2 * i + 1]);
    vf.z = pk(fl[2 * i], fl[2 * i + 1]);
    vf.w = pk(fl[8 + 2 * i], fl[8 + 2 * i + 1]);
    g_tbl[0][o][t] = ve;
    g_tbl[1][o][t] = vf;
}

#define MMA(c0,c1,c2,c3,a0,a1,a2,a3,b0,b1) \
    asm volatile("mma.sync.aligned.m16n8k16.row.col.f32.bf16.bf16.f32 " \
        "{%0,%1,%2,%3}, {%4,%5,%6,%7}, {%8,%9}, {%0,%1,%2,%3};" \
        : "+f"(c0), "+f"(c1), "+f"(c2), "+f"(c3) \
        : "r"(a0), "r"(a1), "r"(a2), "r"(a3), "r"(b0), "r"(b1))

__global__ __launch_bounds__(256) void fm_mma_kernel(
    const float* __restrict__ A, float* __restrict__ out)
{
    extern __shared__ char sm[];
    // copy both tables (1792 uint4, contiguous in g_tbl)
    {
        const uint4* src = &g_tbl[0][0][0];
        uint4* dst = reinterpret_cast<uint4*>(sm);
        for (int j = threadIdx.x; j < 2 * NOCT * 32; j += 256) dst[j] = src[j];
    }

    uint32_t sbase;
    asm("{ .reg .u64 t; cvta.to.shared.u64 t, %1; cvt.u32.u64 %0, t; }"
        : "=r"(sbase) : "l"(sm));

    const int tid = threadIdx.x;
    const int t = tid & 31;
    const int w = tid >> 5;          // warp 0..7
    const int g = t >> 2;            // 0..7
    const int i = t & 3;             // 0..3
    const int px0 = blockIdx.x * 128;
    const int pxA = px0 + w * 16 + g;
    const int pxB = pxA + 8;

    // ---- A fragments (built once) ----
    const int p0 = 2 * i, p1 = 2 * i + 1;
    const int p2 = 2 * i + 8, p3 = 2 * i + 9;
    float vA0 = __ldg(A + (size_t)p0 * NPIX + pxA);
    float vA1 = __ldg(A + (size_t)p1 * NPIX + pxA);
    float vB0 = __ldg(A + (size_t)p0 * NPIX + pxB);
    float vB1 = __ldg(A + (size_t)p1 * NPIX + pxB);
    float vA2 = (i < 2) ? __ldg(A + (size_t)p2 * NPIX + pxA) : 0.0f;
    float vA3 = (i < 2) ? __ldg(A + (size_t)p3 * NPIX + pxA) : 0.0f;
    float vB2 = (i < 2) ? __ldg(A + (size_t)p2 * NPIX + pxB) : 0.0f;
    float vB3 = (i < 2) ? __ldg(A + (size_t)p3 * NPIX + pxB) : 0.0f;

#define SPLIT(v, h, l) float h = __bfloat162float(__float2bfloat16(v)); float l = (v) - h;
    SPLIT(vA0, hA0, lA0) SPLIT(vA1, hA1, lA1) SPLIT(vA2, hA2, lA2) SPLIT(vA3, hA3, lA3)
    SPLIT(vB0, hB0, lB0) SPLIT(vB1, hB1, lB1) SPLIT(vB2, hB2, lB2) SPLIT(vB3, hB3, lB3)
    float sA0 = vA0 * vA0, sA1 = vA1 * vA1, sA2 = vA2 * vA2, sA3 = vA3 * vA3;
    float sB0 = vB0 * vB0, sB1 = vB1 * vB1, sB2 = vB2 * vB2, sB3 = vB3 * vB3;
    SPLIT(sA0, hsA0, lsA0) SPLIT(sA1, hsA1, lsA1) SPLIT(sA2, hsA2, lsA2) SPLIT(sA3, hsA3, lsA3)
    SPLIT(sB0, hsB0, lsB0) SPLIT(sB1, hsB1, lsB1) SPLIT(sB2, hsB2, lsB2) SPLIT(sB3, hsB3, lsB3)

    uint32_t aH0 = pk(vA0, vA1), aH1 = pk(vB0, vB1), aH2 = pk(vA2, vA3), aH3 = pk(vB2, vB3);
    uint32_t aL0 = pk(lA0, lA1), aL1 = pk(lB0, lB1), aL2 = pk(lA2, lA3), aL3 = pk(lB2, lB3);
    uint32_t sH0 = pk(sA0, sA1), sH1 = pk(sB0, sB1), sH2 = pk(sA2, sA3), sH3 = pk(sB2, sB3);
    uint32_t sL0 = pk(lsA0, lsA1), sL1 = pk(lsB0, lsB1), sL2 = pk(lsA2, lsA3), sL3 = pk(lsB2, lsB3);

    __syncthreads();   // tables visible

#pragma unroll 1
    for (int o = 0; o < NOCT; o++) {
        // B fragments: 2x LDS.128 from fragment-order tables
        const uint4 ue = *reinterpret_cast<const uint4*>(sm + SM_TBLE + o * 512 + t * 16);
        const uint4 uf = *reinterpret_cast<const uint4*>(sm + SM_TBLF + o * 512 + t * 16);

        float cl0 = 0.f, cl1 = 0.f, cl2 = 0.f, cl3 = 0.f;
        float cq0 = 0.f, cq1 = 0.f, cq2 = 0.f, cq3 = 0.f;
        MMA(cl0, cl1, cl2, cl3, aH0, aH1, aH2, aH3, ue.x, ue.y);  // ah*eh
        MMA(cl0, cl1, cl2, cl3, aL0, aL1, aL2, aL3, ue.x, ue.y);  // al*eh
        MMA(cl0, cl1, cl2, cl3, aH0, aH1, aH2, aH3, ue.z, ue.w);  // ah*el
        MMA(cq0, cq1, cq2, cq3, sH0, sH1, sH2, sH3, uf.x, uf.y);  // sh*fh
        MMA(cq0, cq1, cq2, cq3, sL0, sL1, sL2, sL3, uf.x, uf.y);  // sl*fh
        MMA(cq0, cq1, cq2, cq3, sH0, sH1, sH2, sH3, uf.z, uf.w);  // sh*fl

        float r0 = fmaf(0.5f, fmaf(cl0, cl0, -cq0), cl0);   // (band 2i,   pxA)
        float r1 = fmaf(0.5f, fmaf(cl1, cl1, -cq1), cl1);   // (band 2i+1, pxA)
        float r2 = fmaf(0.5f, fmaf(cl2, cl2, -cq2), cl2);   // (band 2i,   pxB)
        float r3 = fmaf(0.5f, fmaf(cl3, cl3, -cq3), cl3);   // (band 2i+1, pxB)

        // buffer free? (its previous reader is octet o-2's bulk group)
        if (o >= 2 && tid < 8)
            asm volatile("cp.async.bulk.wait_group.read 1;" ::: "memory");
        __syncthreads();

        // stage tile [8 bands][128 px], pitch 132 floats (conflict-free)
        float* buf = reinterpret_cast<float*>(sm + SM_BUF + (o & 1) * BUF_BYTES);
        const int pxl = w * 16 + g;
        buf[(2 * i) * BUF_PITCH_W + pxl]         = r0;
        buf[(2 * i + 1) * BUF_PITCH_W + pxl]     = r1;
        buf[(2 * i) * BUF_PITCH_W + pxl + 8]     = r2;
        buf[(2 * i + 1) * BUF_PITCH_W + pxl + 8] = r3;

        asm volatile("fence.proxy.async.shared::cta;" ::: "memory");
        __syncthreads();

        if (tid < 8) {
            uint32_t saddr = sbase + SM_BUF + (o & 1) * BUF_BYTES
                           + (uint32_t)tid * (BUF_PITCH_W * 4);
            const float* gdst = out + (size_t)(o * 8 + tid) * NPIX + px0;
            asm volatile(
                "cp.async.bulk.global.shared::cta.bulk_group [%0], [%1], 512;"
                :: "l"(gdst), "r"(saddr) : "memory");
            asm volatile("cp.async.bulk.commit_group;" ::: "memory");
        }
    }
    if (tid < 8)
        asm volatile("cp.async.bulk.wait_group 0;" ::: "memory");
}

extern "C" void kernel_launch(void* const* d_in, const int* in_sizes, int n_in,
                              void* d_out, int out_size)
{
    const float* E = (const float*)d_in[0];
    const float* A = (const float*)d_in[1];
    if (in_sizes[0] > in_sizes[1]) {
        E = (const float*)d_in[1];
        A = (const float*)d_in[0];
    }
    float* out = (float*)d_out;

    cudaFuncSetAttribute(fm_mma_kernel,
                         cudaFuncAttributeMaxDynamicSharedMemorySize, SM_TOTAL);

    prep_kernel<<<7, 128>>>(E);
    fm_mma_kernel<<<NPIX / 128, 256, SM_TOTAL>>>(A, out);
}